// round 9
// baseline (speedup 1.0000x reference)
#include <cuda_runtime.h>
#include <cuda_fp16.h>
#include <math.h>
#include <stdint.h>

#define Bsz   4
#define Nseq  2048
#define Emb   512
#define Hn    8
#define HDm   64
#define HID   1536
#define ROWS  (Bsz * Nseq)   // 8192

// ---------------- scratch (device globals; no allocation allowed) ----------
__device__ __half g_xnh [ROWS * Emb];        // LN1 out (fp16)
__device__ float  g_qkv [ROWS * 3 * Emb];    // QKV GEMM out (fp32)
__device__ float  g_attn[ROWS * Emb];        // attention out (fp32)
__device__ float  g_x1  [ROWS * Emb];        // residual after attention (fp32)
__device__ __half g_xn2h[ROWS * Emb];        // LN2 out (fp16)
__device__ __half g_hidh[ROWS * HID];        // FFN hidden (fp16)
__device__ __half g_wt1 [3 * Emb * Emb];     // qkv_w^T fp16 [1536,512]
__device__ __half g_wt2 [HID * Emb];         // fc1_w^T fp16 [1536,512]
__device__ __half g_wt3 [Emb * HID];         // fc2_w^T fp16 [512,1536]

// ---------------- helpers ----------------------------------------------------
__device__ __forceinline__ float gelu_exact(float x) {
    return 0.5f * x * (1.0f + erff(x * 0.70710678118654752f));
}
__device__ __forceinline__ float tf32r(float x) {
    unsigned u;
    asm("cvt.rna.tf32.f32 %0, %1;" : "=r"(u) : "f"(x));
    return __uint_as_float(u);
}
__device__ __forceinline__ float4 tf32r4(float4 v) {
    float4 r;
    r.x = tf32r(v.x); r.y = tf32r(v.y); r.z = tf32r(v.z); r.w = tf32r(v.w);
    return r;
}
__device__ __forceinline__ void mma_tf32(
    float* d, const unsigned* a, const unsigned* b)
{
    asm volatile(
        "mma.sync.aligned.m16n8k8.row.col.f32.tf32.tf32.f32 "
        "{%0,%1,%2,%3}, {%4,%5,%6,%7}, {%8,%9}, {%0,%1,%2,%3};"
        : "+f"(d[0]), "+f"(d[1]), "+f"(d[2]), "+f"(d[3])
        : "r"(a[0]), "r"(a[1]), "r"(a[2]), "r"(a[3]),
          "r"(b[0]), "r"(b[1]));
}
__device__ __forceinline__ void mma_f16(
    float* d, const unsigned* a, const unsigned* b)
{
    asm volatile(
        "mma.sync.aligned.m16n8k16.row.col.f32.f16.f16.f32 "
        "{%0,%1,%2,%3}, {%4,%5,%6,%7}, {%8,%9}, {%0,%1,%2,%3};"
        : "+f"(d[0]), "+f"(d[1]), "+f"(d[2]), "+f"(d[3])
        : "r"(a[0]), "r"(a[1]), "r"(a[2]), "r"(a[3]),
          "r"(b[0]), "r"(b[1]));
}

// ---------------- LayerNorm: fp32 in (+optional resid), fp16 out -------------
__global__ void __launch_bounds__(256) ln_kernel(
    const float* __restrict__ x, const float* __restrict__ resid,
    const float* __restrict__ g, const float* __restrict__ bb,
    __half* __restrict__ out, float* __restrict__ xsum)
{
    int row = blockIdx.x;
    int tid = threadIdx.x;
    const float2* xr = (const float2*)(x + (size_t)row * Emb);
    float2 v = xr[tid];
    if (resid) {
        const float2* rr = (const float2*)(resid + (size_t)row * Emb);
        float2 r = rr[tid];
        v.x += r.x; v.y += r.y;
        ((float2*)(xsum + (size_t)row * Emb))[tid] = v;
    }
    float s  = v.x + v.y;
    float sq = v.x * v.x + v.y * v.y;
    #pragma unroll
    for (int o = 16; o > 0; o >>= 1) {
        s  += __shfl_xor_sync(0xffffffffu, s,  o);
        sq += __shfl_xor_sync(0xffffffffu, sq, o);
    }
    __shared__ float ss[8], sqs[8];
    int w = tid >> 5, lane = tid & 31;
    if (lane == 0) { ss[w] = s; sqs[w] = sq; }
    __syncthreads();
    float st = 0.f, sqt = 0.f;
    #pragma unroll
    for (int i = 0; i < 8; i++) { st += ss[i]; sqt += sqs[i]; }
    float mu   = st * (1.0f / Emb);
    float var  = sqt * (1.0f / Emb) - mu * mu;
    float rstd = rsqrtf(var + 1e-5f);
    float2 gg  = ((const float2*)g)[tid];
    float2 bv  = ((const float2*)bb)[tid];
    float ox = (v.x - mu) * rstd * gg.x + bv.x;
    float oy = (v.y - mu) * rstd * gg.y + bv.y;
    ((__half2*)(out + (size_t)row * Emb))[tid] = __floats2half2_rn(ox, oy);
}

// ---------------- weight transpose: W[K,N] fp32 -> Wt[N,K] fp16 ---------------
__global__ void __launch_bounds__(256) transpose_h_kernel(
    const float* __restrict__ W, __half* __restrict__ Wt, int K, int N)
{
    __shared__ float t[32][33];
    int tx = threadIdx.x & 31, ty = threadIdx.x >> 5;   // ty 0..7
    int k0 = blockIdx.y * 32, n0 = blockIdx.x * 32;
    #pragma unroll
    for (int i = 0; i < 4; i++)
        t[ty + 8 * i][tx] = W[(size_t)(k0 + ty + 8 * i) * N + n0 + tx];
    __syncthreads();
    #pragma unroll
    for (int i = 0; i < 4; i++)
        Wt[(size_t)(n0 + ty + 8 * i) * K + k0 + tx] =
            __float2half_rn(t[tx][ty + 8 * i]);
}

// ---------------- fp16 mma.sync GEMM: 128-thread CTA, tile 128x128 ------------
// C[M,N] = A[M,K](fp16) @ Wt[N,K](fp16)^T + bias (+gelu)(+resid)
// 4 warps = 2(wm) x 2(wn), warp tile 64x64 (verified R7 fragment pattern).
// BK=32 halves = 16 words/row payload; row stride 20 words. Banks:
// 20g+q mod 32 covers 8 distinct quads -> frag LDS conflict-free.
// Each thread stages ONE 128-row tile row per operand: 4x uint4 = 32 halves.
// SMEM 40KB/CTA double-buffered -> 2+ CTAs/SM (cross-CTA latency hiding).
#define RSW 20                                  // row stride in 4B words
#define ATW (128 * RSW)                         // words per A (or B) buffer
#define GEMM_SMEM (4 * ATW * 4)                 // As0,As1,Bs0,Bs1 = 40960 B

template<int ACT, int OUTH, bool RES>
__global__ void __launch_bounds__(128) h16_gemm_kernel(
    const __half* __restrict__ A, const __half* __restrict__ Bt,
    const float* __restrict__ bias, const float* __restrict__ R,
    void* __restrict__ Cv, int K, int N)
{
    extern __shared__ unsigned smw[];
    unsigned* As = smw;                 // [2][ATW]
    unsigned* Bs = smw + 2 * ATW;       // [2][ATW]

    int tid  = threadIdx.x;
    int lane = tid & 31;
    int wid  = tid >> 5;
    int wm   = wid & 1;        // rows wm*64
    int wn   = wid >> 1;       // cols wn*64
    int bm   = blockIdx.y, bn = blockIdx.x;
    int g    = lane >> 2, q = lane & 3;

    // one thread streams one full row slice (32 halves = 4 uint4) per operand
    const __half* Ag = A  + (size_t)(bm * 128 + tid) * K;
    const __half* Bg = Bt + (size_t)(bn * 128 + tid) * K;

    uint4 pa[4], pb[4];
    #define LOAD_TILE(k0)                                                    \
        {                                                                    \
            _Pragma("unroll")                                                \
            for (int j = 0; j < 4; j++) {                                    \
                pa[j] = *(const uint4*)(Ag + (k0) + j * 8);                  \
                pb[j] = *(const uint4*)(Bg + (k0) + j * 8);                  \
            }                                                                \
        }
    #define STORE_TILE(buf)                                                  \
        {                                                                    \
            _Pragma("unroll")                                                \
            for (int j = 0; j < 4; j++) {                                    \
                *(uint4*)&As[(buf) * ATW + tid * RSW + j * 4] = pa[j];       \
                *(uint4*)&Bs[(buf) * ATW + tid * RSW + j * 4] = pb[j];       \
            }                                                                \
        }

    float acc[4][8][4] = {};

    LOAD_TILE(0);
    STORE_TILE(0);
    __syncthreads();

    int NT = K / 32;
    for (int it = 0; it < NT; it++) {
        int nxt = it + 1;
        if (nxt < NT) LOAD_TILE(nxt * 32);

        const unsigned* asu = As + (it & 1) * ATW + (wm * 64) * RSW;
        const unsigned* bsu = Bs + (it & 1) * ATW + (wn * 64) * RSW;
        #pragma unroll
        for (int kg = 0; kg < 2; kg++) {
            int kk = kg * 8;
            unsigned a[4][4], b[8][2];
            #pragma unroll
            for (int mf = 0; mf < 4; mf++) {
                a[mf][0] = asu[(mf * 16 + g)     * RSW + kk + q];
                a[mf][1] = asu[(mf * 16 + g + 8) * RSW + kk + q];
                a[mf][2] = asu[(mf * 16 + g)     * RSW + kk + q + 4];
                a[mf][3] = asu[(mf * 16 + g + 8) * RSW + kk + q + 4];
            }
            #pragma unroll
            for (int nf = 0; nf < 8; nf++) {
                b[nf][0] = bsu[(nf * 8 + g) * RSW + kk + q];
                b[nf][1] = bsu[(nf * 8 + g) * RSW + kk + q + 4];
            }
            #pragma unroll
            for (int mf = 0; mf < 4; mf++)
                #pragma unroll
                for (int nf = 0; nf < 8; nf++)
                    mma_f16(acc[mf][nf], a[mf], b[nf]);
        }

        __syncthreads();
        if (nxt < NT) {
            STORE_TILE(nxt & 1);
            __syncthreads();
        }
    }

    // epilogue (verified R7)
    int row0 = bm * 128 + wm * 64 + g;
    int col0 = bn * 128 + wn * 64 + 2 * q;
    #pragma unroll
    for (int nf = 0; nf < 8; nf++) {
        int c = col0 + nf * 8;
        float bx = bias[c], by = bias[c + 1];
        #pragma unroll
        for (int mf = 0; mf < 4; mf++) {
            int r0 = row0 + mf * 16;
            float v0x = acc[mf][nf][0] + bx;
            float v0y = acc[mf][nf][1] + by;
            float v1x = acc[mf][nf][2] + bx;
            float v1y = acc[mf][nf][3] + by;
            if (ACT == 1) {
                v0x = gelu_exact(v0x); v0y = gelu_exact(v0y);
                v1x = gelu_exact(v1x); v1y = gelu_exact(v1y);
            }
            if (OUTH) {
                __half* C = (__half*)Cv;
                *(__half2*)&C[(size_t)r0 * N + c]       = __floats2half2_rn(v0x, v0y);
                *(__half2*)&C[(size_t)(r0 + 8) * N + c] = __floats2half2_rn(v1x, v1y);
            } else {
                float* C = (float*)Cv;
                if (RES) {
                    const float2 r0v = *(const float2*)&R[(size_t)r0 * N + c];
                    const float2 r1v = *(const float2*)&R[(size_t)(r0 + 8) * N + c];
                    v0x += r0v.x; v0y += r0v.y;
                    v1x += r1v.x; v1y += r1v.y;
                }
                float2 o0 = {v0x, v0y}, o1 = {v1x, v1y};
                *(float2*)&C[(size_t)r0 * N + c]       = o0;
                *(float2*)&C[(size_t)(r0 + 8) * N + c] = o1;
            }
        }
    }
    #undef LOAD_TILE
    #undef STORE_TILE
}

// ---------------- flash attention, TF32 mma.sync (verified R3/R6) ------------
#define QST 68
#define KST 68
#define VST 72
#define PST 68
#define ATTN_SMEM ((64 * QST + 64 * KST + 64 * VST + 64 * PST) * 4)

__global__ void __launch_bounds__(128) attn_mma_kernel(
    const float* __restrict__ qkv, float* __restrict__ out)
{
    extern __shared__ float sm[];
    float* Qs = sm;
    float* Ks = Qs + 64 * QST;
    float* Vs = Ks + 64 * KST;
    float* Ps = Vs + 64 * VST;

    int tid  = threadIdx.x;
    int lane = tid & 31;
    int w    = tid >> 5;
    int g    = lane >> 2, q = lane & 3;

    int bh = blockIdx.y;
    int b  = bh >> 3, h = bh & 7;
    int q0 = blockIdx.x * 64;
    const float* base = qkv + (size_t)b * Nseq * (3 * Emb) + h * (3 * HDm);

    #pragma unroll
    for (int i = 0; i < 8; i++) {
        int fi  = tid + i * 128;
        int row = fi >> 4;
        int c4  = (fi & 15) * 4;
        float4 v = *(const float4*)(base + (size_t)(q0 + row) * (3 * Emb) + c4);
        *(float4*)&Qs[row * QST + c4] = tf32r4(v);
    }

    float O[8][4] = {};
    float m0 = -1e30f, m1 = -1e30f, l0 = 0.f, l1 = 0.f;

    for (int kb = 0; kb < Nseq / 64; kb++) {
        __syncthreads();
        #pragma unroll
        for (int i = 0; i < 8; i++) {
            int fi  = tid + i * 128;
            int row = fi >> 4;
            int c4  = (fi & 15) * 4;
            const float* gp = base + (size_t)(kb * 64 + row) * (3 * Emb);
            *(float4*)&Ks[row * KST + c4] = tf32r4(*(const float4*)(gp + HDm + c4));
            *(float4*)&Vs[row * VST + c4] = tf32r4(*(const float4*)(gp + 2 * HDm + c4));
        }
        __syncthreads();

        const unsigned* qsu = (const unsigned*)Qs + (w * 16) * QST;
        unsigned af[8][4];
        #pragma unroll
        for (int k8 = 0; k8 < 8; k8++) {
            int kk = k8 * 8;
            af[k8][0] = qsu[(g)     * QST + kk + q];
            af[k8][1] = qsu[(g + 8) * QST + kk + q];
            af[k8][2] = qsu[(g)     * QST + kk + q + 4];
            af[k8][3] = qsu[(g + 8) * QST + kk + q + 4];
        }
        float sacc[8][4] = {};
        const unsigned* ksu = (const unsigned*)Ks;
        #pragma unroll
        for (int nf = 0; nf < 8; nf++) {
            #pragma unroll
            for (int k8 = 0; k8 < 8; k8++) {
                unsigned bfr[2];
                bfr[0] = ksu[(nf * 8 + g) * KST + k8 * 8 + q];
                bfr[1] = ksu[(nf * 8 + g) * KST + k8 * 8 + q + 4];
                mma_tf32(sacc[nf], af[k8], bfr);
            }
        }

        float mx0 = -1e30f, mx1 = -1e30f;
        #pragma unroll
        for (int nf = 0; nf < 8; nf++) {
            sacc[nf][0] *= 0.125f; sacc[nf][1] *= 0.125f;
            sacc[nf][2] *= 0.125f; sacc[nf][3] *= 0.125f;
            mx0 = fmaxf(mx0, fmaxf(sacc[nf][0], sacc[nf][1]));
            mx1 = fmaxf(mx1, fmaxf(sacc[nf][2], sacc[nf][3]));
        }
        mx0 = fmaxf(mx0, __shfl_xor_sync(0xffffffffu, mx0, 1));
        mx0 = fmaxf(mx0, __shfl_xor_sync(0xffffffffu, mx0, 2));
        mx1 = fmaxf(mx1, __shfl_xor_sync(0xffffffffu, mx1, 1));
        mx1 = fmaxf(mx1, __shfl_xor_sync(0xffffffffu, mx1, 2));

        float mn0 = fmaxf(m0, mx0), mn1 = fmaxf(m1, mx1);
        float al0 = __expf(m0 - mn0), al1 = __expf(m1 - mn1);
        m0 = mn0; m1 = mn1;

        float rs0 = 0.f, rs1 = 0.f;
        float* pw = Ps + (w * 16) * PST;
        #pragma unroll
        for (int nf = 0; nf < 8; nf++) {
            float p0 = __expf(sacc[nf][0] - mn0);
            float p1 = __expf(sacc[nf][1] - mn0);
            float p2 = __expf(sacc[nf][2] - mn1);
            float p3 = __expf(sacc[nf][3] - mn1);
            rs0 += p0 + p1; rs1 += p2 + p3;
            pw[(g)     * PST + nf * 8 + 2 * q]     = tf32r(p0);
            pw[(g)     * PST + nf * 8 + 2 * q + 1] = tf32r(p1);
            pw[(g + 8) * PST + nf * 8 + 2 * q]     = tf32r(p2);
            pw[(g + 8) * PST + nf * 8 + 2 * q + 1] = tf32r(p3);
        }
        rs0 += __shfl_xor_sync(0xffffffffu, rs0, 1);
        rs0 += __shfl_xor_sync(0xffffffffu, rs0, 2);
        rs1 += __shfl_xor_sync(0xffffffffu, rs1, 1);
        rs1 += __shfl_xor_sync(0xffffffffu, rs1, 2);
        l0 = l0 * al0 + rs0;
        l1 = l1 * al1 + rs1;

        #pragma unroll
        for (int df = 0; df < 8; df++) {
            O[df][0] *= al0; O[df][1] *= al0;
            O[df][2] *= al1; O[df][3] *= al1;
        }
        __syncwarp();

        const unsigned* psu = (const unsigned*)Ps + (w * 16) * PST;
        unsigned pf[8][4];
        #pragma unroll
        for (int k8 = 0; k8 < 8; k8++) {
            int kk = k8 * 8;
            pf[k8][0] = psu[(g)     * PST + kk + q];
            pf[k8][1] = psu[(g + 8) * PST + kk + q];
            pf[k8][2] = psu[(g)     * PST + kk + q + 4];
            pf[k8][3] = psu[(g + 8) * PST + kk + q + 4];
        }
        const unsigned* vsu = (const unsigned*)Vs;
        #pragma unroll
        for (int df = 0; df < 8; df++) {
            #pragma unroll
            for (int k8 = 0; k8 < 8; k8++) {
                unsigned bfr[2];
                bfr[0] = vsu[(k8 * 8 + q)     * VST + df * 8 + g];
                bfr[1] = vsu[(k8 * 8 + q + 4) * VST + df * 8 + g];
                mma_tf32(O[df], pf[k8], bfr);
            }
        }
    }

    float inv0 = 1.0f / l0, inv1 = 1.0f / l1;
    int r0 = q0 + w * 16 + g;
    int r1 = r0 + 8;
    #pragma unroll
    for (int df = 0; df < 8; df++) {
        int c = h * HDm + df * 8 + 2 * q;
        float2 o0 = {O[df][0] * inv0, O[df][1] * inv0};
        float2 o1 = {O[df][2] * inv1, O[df][3] * inv1};
        *(float2*)&out[((size_t)b * Nseq + r0) * Emb + c] = o0;
        *(float2*)&out[((size_t)b * Nseq + r1) * Emb + c] = o1;
    }
}

// ---------------- launch ------------------------------------------------------
extern "C" void kernel_launch(void* const* d_in, const int* in_sizes, int n_in,
                              void* d_out, int out_size)
{
    (void)in_sizes; (void)n_in; (void)out_size;
    const float* x        = (const float*)d_in[0];
    const float* qkv_w    = (const float*)d_in[1];
    const float* qkv_b    = (const float*)d_in[2];
    const float* fc1_w    = (const float*)d_in[3];
    const float* fc1_b    = (const float*)d_in[4];
    const float* fc2_w    = (const float*)d_in[5];
    const float* fc2_b    = (const float*)d_in[6];
    const float* ln_att_g = (const float*)d_in[7];
    const float* ln_att_b = (const float*)d_in[8];
    const float* ln_ffn_g = (const float*)d_in[9];
    const float* ln_ffn_b = (const float*)d_in[10];
    float* out = (float*)d_out;

    __half *xnh, *xn2h, *hidh, *wt1, *wt2, *wt3;
    float *qkv, *attn, *x1;
    cudaGetSymbolAddress((void**)&xnh,  g_xnh);
    cudaGetSymbolAddress((void**)&qkv,  g_qkv);
    cudaGetSymbolAddress((void**)&attn, g_attn);
    cudaGetSymbolAddress((void**)&x1,   g_x1);
    cudaGetSymbolAddress((void**)&xn2h, g_xn2h);
    cudaGetSymbolAddress((void**)&hidh, g_hidh);
    cudaGetSymbolAddress((void**)&wt1,  g_wt1);
    cudaGetSymbolAddress((void**)&wt2,  g_wt2);
    cudaGetSymbolAddress((void**)&wt3,  g_wt3);

    cudaFuncSetAttribute(attn_mma_kernel,
                         cudaFuncAttributeMaxDynamicSharedMemorySize, ATTN_SMEM);
    cudaFuncSetAttribute(h16_gemm_kernel<0, 0, false>,
                         cudaFuncAttributeMaxDynamicSharedMemorySize, GEMM_SMEM);
    cudaFuncSetAttribute(h16_gemm_kernel<1, 1, false>,
                         cudaFuncAttributeMaxDynamicSharedMemorySize, GEMM_SMEM);
    cudaFuncSetAttribute(h16_gemm_kernel<0, 0, true>,
                         cudaFuncAttributeMaxDynamicSharedMemorySize, GEMM_SMEM);

    // 0) weight transposes to fp16 [N,K]
    transpose_h_kernel<<<dim3(1536 / 32, 512 / 32), 256>>>(qkv_w, wt1, 512, 1536);
    transpose_h_kernel<<<dim3(1536 / 32, 512 / 32), 256>>>(fc1_w, wt2, 512, 1536);
    transpose_h_kernel<<<dim3(512 / 32, 1536 / 32), 256>>>(fc2_w, wt3, 1536, 512);

    // 1) LN1 -> fp16
    ln_kernel<<<ROWS, 256>>>(x, nullptr, ln_att_g, ln_att_b, xnh, nullptr);

    // 2) QKV GEMM (fp16 in, fp32 out): [8192,512] x [512,1536]
    h16_gemm_kernel<0, 0, false><<<dim3(1536 / 128, ROWS / 128), 128, GEMM_SMEM>>>(
        xnh, wt1, qkv_b, nullptr, qkv, Emb, 3 * Emb);

    // 3) attention (tf32, unchanged) -> fp32
    attn_mma_kernel<<<dim3(Nseq / 64, Bsz * Hn), 128, ATTN_SMEM>>>(qkv, attn);

    // 4) residual + LN2 -> xn2 fp16, x1 fp32
    ln_kernel<<<ROWS, 256>>>(attn, x, ln_ffn_g, ln_ffn_b, xn2h, x1);

    // 5) FC1 + GELU (fp16 in, fp16 out)
    h16_gemm_kernel<1, 1, false><<<dim3(HID / 128, ROWS / 128), 128, GEMM_SMEM>>>(
        xn2h, wt2, fc1_b, nullptr, hidh, Emb, HID);

    // 6) FC2 + bias + residual (fp16 in, fp32 out)
    h16_gemm_kernel<0, 0, true><<<dim3(Emb / 128, ROWS / 128), 128, GEMM_SMEM>>>(
        hidh, wt3, fc2_b, x1, out, HID, Emb);
}

// round 11
// speedup vs baseline: 1.4302x; 1.4302x over previous
#include <cuda_runtime.h>
#include <cuda_fp16.h>
#include <math.h>
#include <stdint.h>

#define Bsz   4
#define Nseq  2048
#define Emb   512
#define Hn    8
#define HDm   64
#define HID   1536
#define ROWS  (Bsz * Nseq)   // 8192

// ---------------- scratch (device globals; no allocation allowed) ----------
__device__ __half g_xnh [ROWS * Emb];        // LN1 out (fp16)
__device__ __half g_qkvh[ROWS * 3 * Emb];    // QKV GEMM out (fp16)
__device__ float  g_attn[ROWS * Emb];        // attention out (fp32)
__device__ float  g_x1  [ROWS * Emb];        // residual after attention (fp32)
__device__ __half g_xn2h[ROWS * Emb];        // LN2 out (fp16)
__device__ __half g_hidh[ROWS * HID];        // FFN hidden (fp16)
__device__ __half g_wt1 [3 * Emb * Emb];     // qkv_w^T fp16 [1536,512]
__device__ __half g_wt2 [HID * Emb];         // fc1_w^T fp16 [1536,512]
__device__ __half g_wt3 [Emb * HID];         // fc2_w^T fp16 [512,1536]

// ---------------- helpers ----------------------------------------------------
__device__ __forceinline__ float gelu_exact(float x) {
    return 0.5f * x * (1.0f + erff(x * 0.70710678118654752f));
}
__device__ __forceinline__ void mma_f16(
    float* d, const unsigned* a, const unsigned* b)
{
    asm volatile(
        "mma.sync.aligned.m16n8k16.row.col.f32.f16.f16.f32 "
        "{%0,%1,%2,%3}, {%4,%5,%6,%7}, {%8,%9}, {%0,%1,%2,%3};"
        : "+f"(d[0]), "+f"(d[1]), "+f"(d[2]), "+f"(d[3])
        : "r"(a[0]), "r"(a[1]), "r"(a[2]), "r"(a[3]),
          "r"(b[0]), "r"(b[1]));
}
__device__ __forceinline__ unsigned packh2(float a, float b) {
    __half2 t = __floats2half2_rn(a, b);
    return *(unsigned*)&t;
}

// ---------------- LayerNorm: fp32 in (+optional resid), fp16 out -------------
__global__ void __launch_bounds__(256) ln_kernel(
    const float* __restrict__ x, const float* __restrict__ resid,
    const float* __restrict__ g, const float* __restrict__ bb,
    __half* __restrict__ out, float* __restrict__ xsum)
{
    int row = blockIdx.x;
    int tid = threadIdx.x;
    const float2* xr = (const float2*)(x + (size_t)row * Emb);
    float2 v = xr[tid];
    if (resid) {
        const float2* rr = (const float2*)(resid + (size_t)row * Emb);
        float2 r = rr[tid];
        v.x += r.x; v.y += r.y;
        ((float2*)(xsum + (size_t)row * Emb))[tid] = v;
    }
    float s  = v.x + v.y;
    float sq = v.x * v.x + v.y * v.y;
    #pragma unroll
    for (int o = 16; o > 0; o >>= 1) {
        s  += __shfl_xor_sync(0xffffffffu, s,  o);
        sq += __shfl_xor_sync(0xffffffffu, sq, o);
    }
    __shared__ float ss[8], sqs[8];
    int w = tid >> 5, lane = tid & 31;
    if (lane == 0) { ss[w] = s; sqs[w] = sq; }
    __syncthreads();
    float st = 0.f, sqt = 0.f;
    #pragma unroll
    for (int i = 0; i < 8; i++) { st += ss[i]; sqt += sqs[i]; }
    float mu   = st * (1.0f / Emb);
    float var  = sqt * (1.0f / Emb) - mu * mu;
    float rstd = rsqrtf(var + 1e-5f);
    float2 gg  = ((const float2*)g)[tid];
    float2 bv  = ((const float2*)bb)[tid];
    float ox = (v.x - mu) * rstd * gg.x + bv.x;
    float oy = (v.y - mu) * rstd * gg.y + bv.y;
    ((__half2*)(out + (size_t)row * Emb))[tid] = __floats2half2_rn(ox, oy);
}

// ---------------- weight transpose: W[K,N] fp32 -> Wt[N,K] fp16 ---------------
__global__ void __launch_bounds__(256) transpose_h_kernel(
    const float* __restrict__ W, __half* __restrict__ Wt, int K, int N)
{
    __shared__ float t[32][33];
    int tx = threadIdx.x & 31, ty = threadIdx.x >> 5;   // ty 0..7
    int k0 = blockIdx.y * 32, n0 = blockIdx.x * 32;
    #pragma unroll
    for (int i = 0; i < 4; i++)
        t[ty + 8 * i][tx] = W[(size_t)(k0 + ty + 8 * i) * N + n0 + tx];
    __syncthreads();
    #pragma unroll
    for (int i = 0; i < 4; i++)
        Wt[(size_t)(n0 + ty + 8 * i) * K + k0 + tx] =
            __float2half_rn(t[tx][ty + 8 * i]);
}

// ---------------- fp16 mma.sync GEMM (verified R7): CTA 128x256 ---------------
// C[M,N] = A[M,K](fp16) @ Wt[N,K](fp16)^T + bias (+gelu)(+resid)
// 8 warps = 2(wm) x 4(wn), warp tile 64x64, BK=64 halves, stride 36 words.
#define RSW 36
#define ATW (128 * RSW)
#define BTW (256 * RSW)
#define GEMM_SMEM ((2 * ATW + 2 * BTW) * 4)     // 110592 B

template<int ACT, int OUTH, bool RES>
__global__ void __launch_bounds__(256) h16_gemm_kernel(
    const __half* __restrict__ A, const __half* __restrict__ Bt,
    const float* __restrict__ bias, const float* __restrict__ R,
    void* __restrict__ Cv, int K, int N)
{
    extern __shared__ unsigned smw[];
    unsigned* As = smw;
    unsigned* Bs = smw + 2 * ATW;

    int tid  = threadIdx.x;
    int lane = tid & 31;
    int wid  = tid >> 5;
    int wm   = wid & 1;
    int wn   = wid >> 1;
    int bm   = blockIdx.y, bn = blockIdx.x;
    int g    = lane >> 2, q = lane & 3;

    int ar = tid >> 1;
    int ah = (tid & 1) * 32;
    const __half* Ag = A + (size_t)(bm * 128 + ar) * K + ah;
    const __half* Bg = Bt + (size_t)(bn * 256 + tid) * K;

    uint4 pa[4], pb[8];
    #define LOAD_TILE(k0)                                                    \
        {                                                                    \
            _Pragma("unroll")                                                \
            for (int j = 0; j < 4; j++)                                      \
                pa[j] = *(const uint4*)(Ag + (k0) + j * 8);                  \
            _Pragma("unroll")                                                \
            for (int j = 0; j < 8; j++)                                      \
                pb[j] = *(const uint4*)(Bg + (k0) + j * 8);                  \
        }
    #define STORE_TILE(buf)                                                  \
        {                                                                    \
            _Pragma("unroll")                                                \
            for (int j = 0; j < 4; j++)                                      \
                *(uint4*)&As[(buf) * ATW + ar * RSW + (tid & 1) * 16 + j * 4]\
                    = pa[j];                                                 \
            _Pragma("unroll")                                                \
            for (int j = 0; j < 8; j++)                                      \
                *(uint4*)&Bs[(buf) * BTW + tid * RSW + j * 4] = pb[j];       \
        }

    float acc[4][8][4] = {};

    LOAD_TILE(0);
    STORE_TILE(0);
    __syncthreads();

    int NT = K / 64;
    for (int it = 0; it < NT; it++) {
        int nxt = it + 1;
        if (nxt < NT) LOAD_TILE(nxt * 64);

        const unsigned* asu = As + (it & 1) * ATW + (wm * 64) * RSW;
        const unsigned* bsu = Bs + (it & 1) * BTW + (wn * 64) * RSW;
        #pragma unroll
        for (int kg = 0; kg < 4; kg++) {
            int kk = kg * 8;
            unsigned a[4][4], b[8][2];
            #pragma unroll
            for (int mf = 0; mf < 4; mf++) {
                a[mf][0] = asu[(mf * 16 + g)     * RSW + kk + q];
                a[mf][1] = asu[(mf * 16 + g + 8) * RSW + kk + q];
                a[mf][2] = asu[(mf * 16 + g)     * RSW + kk + q + 4];
                a[mf][3] = asu[(mf * 16 + g + 8) * RSW + kk + q + 4];
            }
            #pragma unroll
            for (int nf = 0; nf < 8; nf++) {
                b[nf][0] = bsu[(nf * 8 + g) * RSW + kk + q];
                b[nf][1] = bsu[(nf * 8 + g) * RSW + kk + q + 4];
            }
            #pragma unroll
            for (int mf = 0; mf < 4; mf++)
                #pragma unroll
                for (int nf = 0; nf < 8; nf++)
                    mma_f16(acc[mf][nf], a[mf], b[nf]);
        }

        __syncthreads();
        if (nxt < NT) {
            STORE_TILE(nxt & 1);
            __syncthreads();
        }
    }

    int row0 = bm * 128 + wm * 64 + g;
    int col0 = bn * 256 + wn * 64 + 2 * q;
    #pragma unroll
    for (int nf = 0; nf < 8; nf++) {
        int c = col0 + nf * 8;
        float bx = bias[c], by = bias[c + 1];
        #pragma unroll
        for (int mf = 0; mf < 4; mf++) {
            int r0 = row0 + mf * 16;
            float v0x = acc[mf][nf][0] + bx;
            float v0y = acc[mf][nf][1] + by;
            float v1x = acc[mf][nf][2] + bx;
            float v1y = acc[mf][nf][3] + by;
            if (ACT == 1) {
                v0x = gelu_exact(v0x); v0y = gelu_exact(v0y);
                v1x = gelu_exact(v1x); v1y = gelu_exact(v1y);
            }
            if (OUTH) {
                __half* C = (__half*)Cv;
                *(__half2*)&C[(size_t)r0 * N + c]       = __floats2half2_rn(v0x, v0y);
                *(__half2*)&C[(size_t)(r0 + 8) * N + c] = __floats2half2_rn(v1x, v1y);
            } else {
                float* C = (float*)Cv;
                if (RES) {
                    const float2 r0v = *(const float2*)&R[(size_t)r0 * N + c];
                    const float2 r1v = *(const float2*)&R[(size_t)(r0 + 8) * N + c];
                    v0x += r0v.x; v0y += r0v.y;
                    v1x += r1v.x; v1y += r1v.y;
                }
                float2 o0 = {v0x, v0y}, o1 = {v1x, v1y};
                *(float2*)&C[(size_t)r0 * N + c]       = o0;
                *(float2*)&C[(size_t)(r0 + 8) * N + c] = o1;
            }
        }
    }
    #undef LOAD_TILE
    #undef STORE_TILE
}

// ---------------- flash attention, fp16 m16n8k16, zero-copy P ----------------
// grid (32, 32), 128 thr = 4 warps; warp w owns Q rows w*16..+15.
// Qs/Ks: [64 rows][64 halves = 32 words payload], stride 36 words
//        (GEMM-verified: 36 = 4 mod 32 -> frag LDS conflict-free).
// Vp: pair-interleaved [32 pairs][64 words], word d of pair p = (V[2p][d],V[2p+1][d]),
//     stride 72 words (8q+g conflict-free, R3-proved).
// P never hits SMEM: S C-frags pack directly into P.V A-frags.
#define QSW 36
#define VPW 72
#define ATTN_SMEM ((64 * QSW + 64 * QSW + 32 * VPW) * 4)   // 27648 B

__global__ void __launch_bounds__(128) attn_h16_kernel(
    const __half* __restrict__ qkv, float* __restrict__ out)
{
    extern __shared__ unsigned smu[];
    unsigned* Qs = smu;
    unsigned* Ks = Qs + 64 * QSW;
    unsigned* Vp = Ks + 64 * QSW;

    int tid  = threadIdx.x;
    int lane = tid & 31;
    int w    = tid >> 5;
    int g    = lane >> 2, q = lane & 3;

    int bh = blockIdx.y;
    int b  = bh >> 3, h = bh & 7;
    int q0 = blockIdx.x * 64;
    const __half* base = qkv + (size_t)b * Nseq * (3 * Emb) + h * (3 * HDm);

    // ---- load Q tile (2 threads per row, 32 halves each) ----
    {
        int r = tid >> 1, o = tid & 1;
        const __half* gq = base + (size_t)(q0 + r) * (3 * Emb) + o * 32;
        #pragma unroll
        for (int j = 0; j < 4; j++)
            *(uint4*)&Qs[r * QSW + o * 16 + j * 4] = *(const uint4*)(gq + j * 8);
    }
    __syncthreads();

    // ---- Q A-fragments (persist for whole CTA) ----
    unsigned af[4][4];
    {
        const unsigned* qsu = Qs + (w * 16) * QSW;
        #pragma unroll
        for (int kg = 0; kg < 4; kg++) {
            int kk = kg * 8;
            af[kg][0] = qsu[(g)     * QSW + kk + q];
            af[kg][1] = qsu[(g + 8) * QSW + kk + q];
            af[kg][2] = qsu[(g)     * QSW + kk + q + 4];
            af[kg][3] = qsu[(g + 8) * QSW + kk + q + 4];
        }
    }

    float O[8][4] = {};
    float m0 = -1e30f, m1 = -1e30f, l0 = 0.f, l1 = 0.f;

    for (int kb = 0; kb < Nseq / 64; kb++) {
        __syncthreads();   // prior iter's Ks/Vp reads complete
        // ---- K tile ----
        {
            int r = tid >> 1, o = tid & 1;
            const __half* gk = base + (size_t)(kb * 64 + r) * (3 * Emb) + HDm + o * 32;
            #pragma unroll
            for (int j = 0; j < 4; j++)
                *(uint4*)&Ks[r * QSW + o * 16 + j * 4] = *(const uint4*)(gk + j * 8);
        }
        // ---- V tile, pair-interleaved ----
        {
            int p = tid >> 2, c = tid & 3;
            const __half* v0 = base + (size_t)(kb * 64 + 2 * p) * (3 * Emb)
                               + 2 * HDm + c * 16;
            const __half* v1 = v0 + 3 * Emb;
            uint4 r0a = *(const uint4*)v0, r0b = *(const uint4*)(v0 + 8);
            uint4 r1a = *(const uint4*)v1, r1b = *(const uint4*)(v1 + 8);
            const __half* h0a = (const __half*)&r0a;
            const __half* h0b = (const __half*)&r0b;
            const __half* h1a = (const __half*)&r1a;
            const __half* h1b = (const __half*)&r1b;
            unsigned ow[16];
            #pragma unroll
            for (int j = 0; j < 8; j++) {
                __half2 t = __halves2half2(h0a[j], h1a[j]);
                ow[j] = *(unsigned*)&t;
            }
            #pragma unroll
            for (int j = 0; j < 8; j++) {
                __half2 t = __halves2half2(h0b[j], h1b[j]);
                ow[8 + j] = *(unsigned*)&t;
            }
            #pragma unroll
            for (int j = 0; j < 4; j++)
                *(uint4*)&Vp[p * VPW + c * 16 + j * 4] = *(uint4*)&ow[j * 4];
        }
        __syncthreads();

        // ---- S = Q K^T : 8 nf x 4 kg fp16 MMAs ----
        float sacc[8][4] = {};
        #pragma unroll
        for (int nf = 0; nf < 8; nf++) {
            #pragma unroll
            for (int kg = 0; kg < 4; kg++) {
                unsigned bfr[2];
                bfr[0] = Ks[(nf * 8 + g) * QSW + kg * 8 + q];
                bfr[1] = Ks[(nf * 8 + g) * QSW + kg * 8 + q + 4];
                mma_f16(sacc[nf], af[kg], bfr);
            }
        }

        // ---- online softmax on C-fragments ----
        float mx0 = -1e30f, mx1 = -1e30f;
        #pragma unroll
        for (int nf = 0; nf < 8; nf++) {
            sacc[nf][0] *= 0.125f; sacc[nf][1] *= 0.125f;
            sacc[nf][2] *= 0.125f; sacc[nf][3] *= 0.125f;
            mx0 = fmaxf(mx0, fmaxf(sacc[nf][0], sacc[nf][1]));
            mx1 = fmaxf(mx1, fmaxf(sacc[nf][2], sacc[nf][3]));
        }
        mx0 = fmaxf(mx0, __shfl_xor_sync(0xffffffffu, mx0, 1));
        mx0 = fmaxf(mx0, __shfl_xor_sync(0xffffffffu, mx0, 2));
        mx1 = fmaxf(mx1, __shfl_xor_sync(0xffffffffu, mx1, 1));
        mx1 = fmaxf(mx1, __shfl_xor_sync(0xffffffffu, mx1, 2));

        float mn0 = fmaxf(m0, mx0), mn1 = fmaxf(m1, mx1);
        float al0 = __expf(m0 - mn0), al1 = __expf(m1 - mn1);
        m0 = mn0; m1 = mn1;

        float rs0 = 0.f, rs1 = 0.f;
        #pragma unroll
        for (int nf = 0; nf < 8; nf++) {
            sacc[nf][0] = __expf(sacc[nf][0] - mn0);
            sacc[nf][1] = __expf(sacc[nf][1] - mn0);
            sacc[nf][2] = __expf(sacc[nf][2] - mn1);
            sacc[nf][3] = __expf(sacc[nf][3] - mn1);
            rs0 += sacc[nf][0] + sacc[nf][1];
            rs1 += sacc[nf][2] + sacc[nf][3];
        }
        rs0 += __shfl_xor_sync(0xffffffffu, rs0, 1);
        rs0 += __shfl_xor_sync(0xffffffffu, rs0, 2);
        rs1 += __shfl_xor_sync(0xffffffffu, rs1, 1);
        rs1 += __shfl_xor_sync(0xffffffffu, rs1, 2);
        l0 = l0 * al0 + rs0;
        l1 = l1 * al1 + rs1;

        // ---- pack P directly into A-fragments (no SMEM round-trip) ----
        unsigned pf[4][4];
        #pragma unroll
        for (int kg = 0; kg < 4; kg++) {
            pf[kg][0] = packh2(sacc[2 * kg][0],     sacc[2 * kg][1]);
            pf[kg][1] = packh2(sacc[2 * kg][2],     sacc[2 * kg][3]);
            pf[kg][2] = packh2(sacc[2 * kg + 1][0], sacc[2 * kg + 1][1]);
            pf[kg][3] = packh2(sacc[2 * kg + 1][2], sacc[2 * kg + 1][3]);
        }

        #pragma unroll
        for (int df = 0; df < 8; df++) {
            O[df][0] *= al0; O[df][1] *= al0;
            O[df][2] *= al1; O[df][3] *= al1;
        }

        // ---- O += P V ----
        #pragma unroll
        for (int df = 0; df < 8; df++) {
            #pragma unroll
            for (int kg = 0; kg < 4; kg++) {
                unsigned bfr[2];
                bfr[0] = Vp[(kg * 8 + q)     * VPW + df * 8 + g];
                bfr[1] = Vp[(kg * 8 + q + 4) * VPW + df * 8 + g];
                mma_f16(O[df], pf[kg], bfr);
            }
        }
    }

    // ---- epilogue ----
    float inv0 = 1.0f / l0, inv1 = 1.0f / l1;
    int r0 = q0 + w * 16 + g;
    int r1 = r0 + 8;
    #pragma unroll
    for (int df = 0; df < 8; df++) {
        int c = h * HDm + df * 8 + 2 * q;
        float2 o0 = {O[df][0] * inv0, O[df][1] * inv0};
        float2 o1 = {O[df][2] * inv1, O[df][3] * inv1};
        *(float2*)&out[((size_t)b * Nseq + r0) * Emb + c] = o0;
        *(float2*)&out[((size_t)b * Nseq + r1) * Emb + c] = o1;
    }
}

// ---------------- launch ------------------------------------------------------
extern "C" void kernel_launch(void* const* d_in, const int* in_sizes, int n_in,
                              void* d_out, int out_size)
{
    (void)in_sizes; (void)n_in; (void)out_size;
    const float* x        = (const float*)d_in[0];
    const float* qkv_w    = (const float*)d_in[1];
    const float* qkv_b    = (const float*)d_in[2];
    const float* fc1_w    = (const float*)d_in[3];
    const float* fc1_b    = (const float*)d_in[4];
    const float* fc2_w    = (const float*)d_in[5];
    const float* fc2_b    = (const float*)d_in[6];
    const float* ln_att_g = (const float*)d_in[7];
    const float* ln_att_b = (const float*)d_in[8];
    const float* ln_ffn_g = (const float*)d_in[9];
    const float* ln_ffn_b = (const float*)d_in[10];
    float* out = (float*)d_out;

    __half *xnh, *qkvh, *xn2h, *hidh, *wt1, *wt2, *wt3;
    float *attn, *x1;
    cudaGetSymbolAddress((void**)&xnh,  g_xnh);
    cudaGetSymbolAddress((void**)&qkvh, g_qkvh);
    cudaGetSymbolAddress((void**)&attn, g_attn);
    cudaGetSymbolAddress((void**)&x1,   g_x1);
    cudaGetSymbolAddress((void**)&xn2h, g_xn2h);
    cudaGetSymbolAddress((void**)&hidh, g_hidh);
    cudaGetSymbolAddress((void**)&wt1,  g_wt1);
    cudaGetSymbolAddress((void**)&wt2,  g_wt2);
    cudaGetSymbolAddress((void**)&wt3,  g_wt3);

    cudaFuncSetAttribute(h16_gemm_kernel<0, 1, false>,
                         cudaFuncAttributeMaxDynamicSharedMemorySize, GEMM_SMEM);
    cudaFuncSetAttribute(h16_gemm_kernel<1, 1, false>,
                         cudaFuncAttributeMaxDynamicSharedMemorySize, GEMM_SMEM);
    cudaFuncSetAttribute(h16_gemm_kernel<0, 0, true>,
                         cudaFuncAttributeMaxDynamicSharedMemorySize, GEMM_SMEM);

    // 0) weight transposes to fp16 [N,K]
    transpose_h_kernel<<<dim3(1536 / 32, 512 / 32), 256>>>(qkv_w, wt1, 512, 1536);
    transpose_h_kernel<<<dim3(1536 / 32, 512 / 32), 256>>>(fc1_w, wt2, 512, 1536);
    transpose_h_kernel<<<dim3(512 / 32, 1536 / 32), 256>>>(fc2_w, wt3, 1536, 512);

    // 1) LN1 -> fp16
    ln_kernel<<<ROWS, 256>>>(x, nullptr, ln_att_g, ln_att_b, xnh, nullptr);

    // 2) QKV GEMM (fp16 in, fp16 out): [8192,512] x [512,1536]
    h16_gemm_kernel<0, 1, false><<<dim3(1536 / 256, ROWS / 128), 256, GEMM_SMEM>>>(
        xnh, wt1, qkv_b, nullptr, qkvh, Emb, 3 * Emb);

    // 3) attention (fp16 mma, zero-copy P) -> fp32
    attn_h16_kernel<<<dim3(Nseq / 64, Bsz * Hn), 128, ATTN_SMEM>>>(qkvh, attn);

    // 4) residual + LN2 -> xn2 fp16, x1 fp32
    ln_kernel<<<ROWS, 256>>>(attn, x, ln_ffn_g, ln_ffn_b, xn2h, x1);

    // 5) FC1 + GELU (fp16 in, fp16 out)
    h16_gemm_kernel<1, 1, false><<<dim3(HID / 256, ROWS / 128), 256, GEMM_SMEM>>>(
        xn2h, wt2, fc1_b, nullptr, hidh, Emb, HID);

    // 6) FC2 + bias + residual (fp16 in, fp32 out)
    h16_gemm_kernel<0, 0, true><<<dim3(Emb / 256, ROWS / 128), 256, GEMM_SMEM>>>(
        hidh, wt3, fc2_b, x1, out, HID, Emb);
}

// round 12
// speedup vs baseline: 1.4394x; 1.0065x over previous
#include <cuda_runtime.h>
#include <cuda_fp16.h>
#include <math.h>
#include <stdint.h>

#define Bsz   4
#define Nseq  2048
#define Emb   512
#define Hn    8
#define HDm   64
#define HID   1536
#define ROWS  (Bsz * Nseq)   // 8192

// ---------------- scratch (device globals; no allocation allowed) ----------
__device__ __half g_xnh [ROWS * Emb];
__device__ __half g_qkvh[ROWS * 3 * Emb];
__device__ float  g_attn[ROWS * Emb];
__device__ float  g_x1  [ROWS * Emb];
__device__ __half g_xn2h[ROWS * Emb];
__device__ __half g_hidh[ROWS * HID];
__device__ __half g_wt1 [3 * Emb * Emb];
__device__ __half g_wt2 [HID * Emb];
__device__ __half g_wt3 [Emb * HID];

// ---------------- helpers ----------------------------------------------------
__device__ __forceinline__ float gelu_exact(float x) {
    return 0.5f * x * (1.0f + erff(x * 0.70710678118654752f));
}
__device__ __forceinline__ void mma_f16(
    float* d, const unsigned* a, const unsigned* b)
{
    asm volatile(
        "mma.sync.aligned.m16n8k16.row.col.f32.f16.f16.f32 "
        "{%0,%1,%2,%3}, {%4,%5,%6,%7}, {%8,%9}, {%0,%1,%2,%3};"
        : "+f"(d[0]), "+f"(d[1]), "+f"(d[2]), "+f"(d[3])
        : "r"(a[0]), "r"(a[1]), "r"(a[2]), "r"(a[3]),
          "r"(b[0]), "r"(b[1]));
}
__device__ __forceinline__ unsigned packh2(float a, float b) {
    __half2 t = __floats2half2_rn(a, b);
    return *(unsigned*)&t;
}

// ---------------- LayerNorm: fp32 in (+optional resid), fp16 out -------------
__global__ void __launch_bounds__(256) ln_kernel(
    const float* __restrict__ x, const float* __restrict__ resid,
    const float* __restrict__ g, const float* __restrict__ bb,
    __half* __restrict__ out, float* __restrict__ xsum)
{
    int row = blockIdx.x;
    int tid = threadIdx.x;
    const float2* xr = (const float2*)(x + (size_t)row * Emb);
    float2 v = xr[tid];
    if (resid) {
        const float2* rr = (const float2*)(resid + (size_t)row * Emb);
        float2 r = rr[tid];
        v.x += r.x; v.y += r.y;
        ((float2*)(xsum + (size_t)row * Emb))[tid] = v;
    }
    float s  = v.x + v.y;
    float sq = v.x * v.x + v.y * v.y;
    #pragma unroll
    for (int o = 16; o > 0; o >>= 1) {
        s  += __shfl_xor_sync(0xffffffffu, s,  o);
        sq += __shfl_xor_sync(0xffffffffu, sq, o);
    }
    __shared__ float ss[8], sqs[8];
    int w = tid >> 5, lane = tid & 31;
    if (lane == 0) { ss[w] = s; sqs[w] = sq; }
    __syncthreads();
    float st = 0.f, sqt = 0.f;
    #pragma unroll
    for (int i = 0; i < 8; i++) { st += ss[i]; sqt += sqs[i]; }
    float mu   = st * (1.0f / Emb);
    float var  = sqt * (1.0f / Emb) - mu * mu;
    float rstd = rsqrtf(var + 1e-5f);
    float2 gg  = ((const float2*)g)[tid];
    float2 bv  = ((const float2*)bb)[tid];
    float ox = (v.x - mu) * rstd * gg.x + bv.x;
    float oy = (v.y - mu) * rstd * gg.y + bv.y;
    ((__half2*)(out + (size_t)row * Emb))[tid] = __floats2half2_rn(ox, oy);
}

// ---------------- weight transpose: W[K,N] fp32 -> Wt[N,K] fp16 ---------------
__global__ void __launch_bounds__(256) transpose_h_kernel(
    const float* __restrict__ W, __half* __restrict__ Wt, int K, int N)
{
    __shared__ float t[32][33];
    int tx = threadIdx.x & 31, ty = threadIdx.x >> 5;
    int k0 = blockIdx.y * 32, n0 = blockIdx.x * 32;
    #pragma unroll
    for (int i = 0; i < 4; i++)
        t[ty + 8 * i][tx] = W[(size_t)(k0 + ty + 8 * i) * N + n0 + tx];
    __syncthreads();
    #pragma unroll
    for (int i = 0; i < 4; i++)
        Wt[(size_t)(n0 + ty + 8 * i) * K + k0 + tx] =
            __float2half_rn(t[tx][ty + 8 * i]);
}

// ---------------- fp16 mma.sync GEMM: CTA 128x256, 1 sync/iter pipeline ------
#define RSW 36
#define ATW (128 * RSW)
#define BTW (256 * RSW)
#define GEMM_SMEM ((2 * ATW + 2 * BTW) * 4)     // 110592 B

template<int ACT, int OUTH, bool RES>
__global__ void __launch_bounds__(256) h16_gemm_kernel(
    const __half* __restrict__ A, const __half* __restrict__ Bt,
    const float* __restrict__ bias, const float* __restrict__ R,
    void* __restrict__ Cv, int K, int N)
{
    extern __shared__ unsigned smw[];
    unsigned* As = smw;
    unsigned* Bs = smw + 2 * ATW;

    int tid  = threadIdx.x;
    int lane = tid & 31;
    int wid  = tid >> 5;
    int wm   = wid & 1;
    int wn   = wid >> 1;
    int bm   = blockIdx.y, bn = blockIdx.x;
    int g    = lane >> 2, q = lane & 3;

    int ar = tid >> 1;
    int ah = (tid & 1) * 32;
    const __half* Ag = A + (size_t)(bm * 128 + ar) * K + ah;
    const __half* Bg = Bt + (size_t)(bn * 256 + tid) * K;

    uint4 pa[4], pb[8];
    #define LOAD_TILE(k0)                                                    \
        {                                                                    \
            _Pragma("unroll")                                                \
            for (int j = 0; j < 4; j++)                                      \
                pa[j] = *(const uint4*)(Ag + (k0) + j * 8);                  \
            _Pragma("unroll")                                                \
            for (int j = 0; j < 8; j++)                                      \
                pb[j] = *(const uint4*)(Bg + (k0) + j * 8);                  \
        }
    #define STORE_TILE(buf)                                                  \
        {                                                                    \
            _Pragma("unroll")                                                \
            for (int j = 0; j < 4; j++)                                      \
                *(uint4*)&As[(buf) * ATW + ar * RSW + (tid & 1) * 16 + j * 4]\
                    = pa[j];                                                 \
            _Pragma("unroll")                                                \
            for (int j = 0; j < 8; j++)                                      \
                *(uint4*)&Bs[(buf) * BTW + tid * RSW + j * 4] = pb[j];       \
        }

    float acc[4][8][4] = {};

    LOAD_TILE(0);

    int NT = K / 64;
    for (int it = 0; it < NT; it++) {
        int buf = it & 1;
        STORE_TILE(buf);
        __syncthreads();
        if (it + 1 < NT) LOAD_TILE((it + 1) * 64);

        const unsigned* asu = As + buf * ATW + (wm * 64) * RSW;
        const unsigned* bsu = Bs + buf * BTW + (wn * 64) * RSW;
        #pragma unroll
        for (int kg = 0; kg < 4; kg++) {
            int kk = kg * 8;
            unsigned a[4][4], b[8][2];
            #pragma unroll
            for (int mf = 0; mf < 4; mf++) {
                a[mf][0] = asu[(mf * 16 + g)     * RSW + kk + q];
                a[mf][1] = asu[(mf * 16 + g + 8) * RSW + kk + q];
                a[mf][2] = asu[(mf * 16 + g)     * RSW + kk + q + 4];
                a[mf][3] = asu[(mf * 16 + g + 8) * RSW + kk + q + 4];
            }
            #pragma unroll
            for (int nf = 0; nf < 8; nf++) {
                b[nf][0] = bsu[(nf * 8 + g) * RSW + kk + q];
                b[nf][1] = bsu[(nf * 8 + g) * RSW + kk + q + 4];
            }
            #pragma unroll
            for (int mf = 0; mf < 4; mf++)
                #pragma unroll
                for (int nf = 0; nf < 8; nf++)
                    mma_f16(acc[mf][nf], a[mf], b[nf]);
        }
    }

    int row0 = bm * 128 + wm * 64 + g;
    int col0 = bn * 256 + wn * 64 + 2 * q;
    #pragma unroll
    for (int nf = 0; nf < 8; nf++) {
        int c = col0 + nf * 8;
        float bx = bias[c], by = bias[c + 1];
        #pragma unroll
        for (int mf = 0; mf < 4; mf++) {
            int r0 = row0 + mf * 16;
            float v0x = acc[mf][nf][0] + bx;
            float v0y = acc[mf][nf][1] + by;
            float v1x = acc[mf][nf][2] + bx;
            float v1y = acc[mf][nf][3] + by;
            if (ACT == 1) {
                v0x = gelu_exact(v0x); v0y = gelu_exact(v0y);
                v1x = gelu_exact(v1x); v1y = gelu_exact(v1y);
            }
            if (OUTH) {
                __half* C = (__half*)Cv;
                *(__half2*)&C[(size_t)r0 * N + c]       = __floats2half2_rn(v0x, v0y);
                *(__half2*)&C[(size_t)(r0 + 8) * N + c] = __floats2half2_rn(v1x, v1y);
            } else {
                float* C = (float*)Cv;
                if (RES) {
                    const float2 r0v = *(const float2*)&R[(size_t)r0 * N + c];
                    const float2 r1v = *(const float2*)&R[(size_t)(r0 + 8) * N + c];
                    v0x += r0v.x; v0y += r0v.y;
                    v1x += r1v.x; v1y += r1v.y;
                }
                float2 o0 = {v0x, v0y}, o1 = {v1x, v1y};
                *(float2*)&C[(size_t)r0 * N + c]       = o0;
                *(float2*)&C[(size_t)(r0 + 8) * N + c] = o1;
            }
        }
    }
    #undef LOAD_TILE
    #undef STORE_TILE
}

// ---------------- flash attention, fp16, zero-copy P, pipelined K/V ----------
// Qs: [64][stride 36]; Ks/Vp double-buffered. 1 __syncthreads per k-block:
// STORE(buf) ; sync ; LOAD(next->regs) ; compute(buf).
#define QSW 36
#define VPW 72
#define KBUF (64 * QSW)
#define VBUF (32 * VPW)
#define ATTN_SMEM ((64 * QSW + 2 * KBUF + 2 * VBUF) * 4)   // 46080 B

__global__ void __launch_bounds__(128) attn_h16_kernel(
    const __half* __restrict__ qkv, float* __restrict__ out)
{
    extern __shared__ unsigned smu[];
    unsigned* Qs = smu;
    unsigned* Ks = Qs + 64 * QSW;          // [2][KBUF]
    unsigned* Vp = Ks + 2 * KBUF;          // [2][VBUF]

    int tid  = threadIdx.x;
    int lane = tid & 31;
    int w    = tid >> 5;
    int g    = lane >> 2, q = lane & 3;

    int bh = blockIdx.y;
    int b  = bh >> 3, h = bh & 7;
    int q0 = blockIdx.x * 64;
    const __half* base = qkv + (size_t)b * Nseq * (3 * Emb) + h * (3 * HDm);

    // ---- load Q tile ----
    {
        int r = tid >> 1, o = tid & 1;
        const __half* gq = base + (size_t)(q0 + r) * (3 * Emb) + o * 32;
        #pragma unroll
        for (int j = 0; j < 4; j++)
            *(uint4*)&Qs[r * QSW + o * 16 + j * 4] = *(const uint4*)(gq + j * 8);
    }
    __syncthreads();

    // ---- Q A-fragments (persist) ----
    unsigned af[4][4];
    {
        const unsigned* qsu = Qs + (w * 16) * QSW;
        #pragma unroll
        for (int kg = 0; kg < 4; kg++) {
            int kk = kg * 8;
            af[kg][0] = qsu[(g)     * QSW + kk + q];
            af[kg][1] = qsu[(g + 8) * QSW + kk + q];
            af[kg][2] = qsu[(g)     * QSW + kk + q + 4];
            af[kg][3] = qsu[(g + 8) * QSW + kk + q + 4];
        }
    }

    // per-thread staging registers for K and V tiles
    int kr = tid >> 1, ko = tid & 1;
    int vp = tid >> 2, vc = tid & 3;
    const __half* gk_base = base + HDm + ko * 32 + (size_t)kr * (3 * Emb);
    const __half* gv_base = base + 2 * HDm + vc * 16 + (size_t)(2 * vp) * (3 * Emb);

    uint4 kreg[4];
    unsigned vw[16];
    #define LOADKV(kb)                                                        \
        {                                                                     \
            const __half* gk = gk_base + (size_t)((kb) * 64) * (3 * Emb);     \
            _Pragma("unroll")                                                 \
            for (int j = 0; j < 4; j++)                                       \
                kreg[j] = *(const uint4*)(gk + j * 8);                        \
            const __half* v0 = gv_base + (size_t)((kb) * 64) * (3 * Emb);     \
            const __half* v1 = v0 + 3 * Emb;                                  \
            uint4 r0a = *(const uint4*)v0, r0b = *(const uint4*)(v0 + 8);     \
            uint4 r1a = *(const uint4*)v1, r1b = *(const uint4*)(v1 + 8);     \
            const __half* h0a = (const __half*)&r0a;                          \
            const __half* h0b = (const __half*)&r0b;                          \
            const __half* h1a = (const __half*)&r1a;                          \
            const __half* h1b = (const __half*)&r1b;                          \
            _Pragma("unroll")                                                 \
            for (int j = 0; j < 8; j++) {                                     \
                __half2 t = __halves2half2(h0a[j], h1a[j]);                   \
                vw[j] = *(unsigned*)&t;                                       \
            }                                                                 \
            _Pragma("unroll")                                                 \
            for (int j = 0; j < 8; j++) {                                     \
                __half2 t = __halves2half2(h0b[j], h1b[j]);                   \
                vw[8 + j] = *(unsigned*)&t;                                   \
            }                                                                 \
        }
    #define STOREKV(buf)                                                      \
        {                                                                     \
            _Pragma("unroll")                                                 \
            for (int j = 0; j < 4; j++)                                       \
                *(uint4*)&Ks[(buf) * KBUF + kr * QSW + ko * 16 + j * 4]       \
                    = kreg[j];                                                \
            _Pragma("unroll")                                                 \
            for (int j = 0; j < 4; j++)                                       \
                *(uint4*)&Vp[(buf) * VBUF + vp * VPW + vc * 16 + j * 4]       \
                    = *(uint4*)&vw[j * 4];                                    \
        }

    float O[8][4] = {};
    float m0 = -1e30f, m1 = -1e30f, l0 = 0.f, l1 = 0.f;

    LOADKV(0);

    const int NKB = Nseq / 64;
    for (int kb = 0; kb < NKB; kb++) {
        int buf = kb & 1;
        STOREKV(buf);
        __syncthreads();
        if (kb + 1 < NKB) LOADKV(kb + 1);

        const unsigned* ksu = Ks + buf * KBUF;
        const unsigned* vsu = Vp + buf * VBUF;

        // ---- S = Q K^T ----
        float sacc[8][4] = {};
        #pragma unroll
        for (int nf = 0; nf < 8; nf++) {
            #pragma unroll
            for (int kg = 0; kg < 4; kg++) {
                unsigned bfr[2];
                bfr[0] = ksu[(nf * 8 + g) * QSW + kg * 8 + q];
                bfr[1] = ksu[(nf * 8 + g) * QSW + kg * 8 + q + 4];
                mma_f16(sacc[nf], af[kg], bfr);
            }
        }

        // ---- online softmax on C-fragments ----
        float mx0 = -1e30f, mx1 = -1e30f;
        #pragma unroll
        for (int nf = 0; nf < 8; nf++) {
            sacc[nf][0] *= 0.125f; sacc[nf][1] *= 0.125f;
            sacc[nf][2] *= 0.125f; sacc[nf][3] *= 0.125f;
            mx0 = fmaxf(mx0, fmaxf(sacc[nf][0], sacc[nf][1]));
            mx1 = fmaxf(mx1, fmaxf(sacc[nf][2], sacc[nf][3]));
        }
        mx0 = fmaxf(mx0, __shfl_xor_sync(0xffffffffu, mx0, 1));
        mx0 = fmaxf(mx0, __shfl_xor_sync(0xffffffffu, mx0, 2));
        mx1 = fmaxf(mx1, __shfl_xor_sync(0xffffffffu, mx1, 1));
        mx1 = fmaxf(mx1, __shfl_xor_sync(0xffffffffu, mx1, 2));

        float mn0 = fmaxf(m0, mx0), mn1 = fmaxf(m1, mx1);
        float al0 = __expf(m0 - mn0), al1 = __expf(m1 - mn1);
        m0 = mn0; m1 = mn1;

        float rs0 = 0.f, rs1 = 0.f;
        #pragma unroll
        for (int nf = 0; nf < 8; nf++) {
            sacc[nf][0] = __expf(sacc[nf][0] - mn0);
            sacc[nf][1] = __expf(sacc[nf][1] - mn0);
            sacc[nf][2] = __expf(sacc[nf][2] - mn1);
            sacc[nf][3] = __expf(sacc[nf][3] - mn1);
            rs0 += sacc[nf][0] + sacc[nf][1];
            rs1 += sacc[nf][2] + sacc[nf][3];
        }
        rs0 += __shfl_xor_sync(0xffffffffu, rs0, 1);
        rs0 += __shfl_xor_sync(0xffffffffu, rs0, 2);
        rs1 += __shfl_xor_sync(0xffffffffu, rs1, 1);
        rs1 += __shfl_xor_sync(0xffffffffu, rs1, 2);
        l0 = l0 * al0 + rs0;
        l1 = l1 * al1 + rs1;

        // ---- pack P into A-frags (zero-copy) ----
        unsigned pf[4][4];
        #pragma unroll
        for (int kg = 0; kg < 4; kg++) {
            pf[kg][0] = packh2(sacc[2 * kg][0],     sacc[2 * kg][1]);
            pf[kg][1] = packh2(sacc[2 * kg][2],     sacc[2 * kg][3]);
            pf[kg][2] = packh2(sacc[2 * kg + 1][0], sacc[2 * kg + 1][1]);
            pf[kg][3] = packh2(sacc[2 * kg + 1][2], sacc[2 * kg + 1][3]);
        }

        #pragma unroll
        for (int df = 0; df < 8; df++) {
            O[df][0] *= al0; O[df][1] *= al0;
            O[df][2] *= al1; O[df][3] *= al1;
        }

        // ---- O += P V ----
        #pragma unroll
        for (int df = 0; df < 8; df++) {
            #pragma unroll
            for (int kg = 0; kg < 4; kg++) {
                unsigned bfr[2];
                bfr[0] = vsu[(kg * 8 + q)     * VPW + df * 8 + g];
                bfr[1] = vsu[(kg * 8 + q + 4) * VPW + df * 8 + g];
                mma_f16(O[df], pf[kg], bfr);
            }
        }
    }

    // ---- epilogue ----
    float inv0 = 1.0f / l0, inv1 = 1.0f / l1;
    int r0 = q0 + w * 16 + g;
    int r1 = r0 + 8;
    #pragma unroll
    for (int df = 0; df < 8; df++) {
        int c = h * HDm + df * 8 + 2 * q;
        float2 o0 = {O[df][0] * inv0, O[df][1] * inv0};
        float2 o1 = {O[df][2] * inv1, O[df][3] * inv1};
        *(float2*)&out[((size_t)b * Nseq + r0) * Emb + c] = o0;
        *(float2*)&out[((size_t)b * Nseq + r1) * Emb + c] = o1;
    }
    #undef LOADKV
    #undef STOREKV
}

// ---------------- launch ------------------------------------------------------
extern "C" void kernel_launch(void* const* d_in, const int* in_sizes, int n_in,
                              void* d_out, int out_size)
{
    (void)in_sizes; (void)n_in; (void)out_size;
    const float* x        = (const float*)d_in[0];
    const float* qkv_w    = (const float*)d_in[1];
    const float* qkv_b    = (const float*)d_in[2];
    const float* fc1_w    = (const float*)d_in[3];
    const float* fc1_b    = (const float*)d_in[4];
    const float* fc2_w    = (const float*)d_in[5];
    const float* fc2_b    = (const float*)d_in[6];
    const float* ln_att_g = (const float*)d_in[7];
    const float* ln_att_b = (const float*)d_in[8];
    const float* ln_ffn_g = (const float*)d_in[9];
    const float* ln_ffn_b = (const float*)d_in[10];
    float* out = (float*)d_out;

    __half *xnh, *qkvh, *xn2h, *hidh, *wt1, *wt2, *wt3;
    float *attn, *x1;
    cudaGetSymbolAddress((void**)&xnh,  g_xnh);
    cudaGetSymbolAddress((void**)&qkvh, g_qkvh);
    cudaGetSymbolAddress((void**)&attn, g_attn);
    cudaGetSymbolAddress((void**)&x1,   g_x1);
    cudaGetSymbolAddress((void**)&xn2h, g_xn2h);
    cudaGetSymbolAddress((void**)&hidh, g_hidh);
    cudaGetSymbolAddress((void**)&wt1,  g_wt1);
    cudaGetSymbolAddress((void**)&wt2,  g_wt2);
    cudaGetSymbolAddress((void**)&wt3,  g_wt3);

    cudaFuncSetAttribute(attn_h16_kernel,
                         cudaFuncAttributeMaxDynamicSharedMemorySize, ATTN_SMEM);
    cudaFuncSetAttribute(h16_gemm_kernel<0, 1, false>,
                         cudaFuncAttributeMaxDynamicSharedMemorySize, GEMM_SMEM);
    cudaFuncSetAttribute(h16_gemm_kernel<1, 1, false>,
                         cudaFuncAttributeMaxDynamicSharedMemorySize, GEMM_SMEM);
    cudaFuncSetAttribute(h16_gemm_kernel<0, 0, true>,
                         cudaFuncAttributeMaxDynamicSharedMemorySize, GEMM_SMEM);

    // 0) weight transposes to fp16 [N,K]
    transpose_h_kernel<<<dim3(1536 / 32, 512 / 32), 256>>>(qkv_w, wt1, 512, 1536);
    transpose_h_kernel<<<dim3(1536 / 32, 512 / 32), 256>>>(fc1_w, wt2, 512, 1536);
    transpose_h_kernel<<<dim3(512 / 32, 1536 / 32), 256>>>(fc2_w, wt3, 1536, 512);

    // 1) LN1 -> fp16
    ln_kernel<<<ROWS, 256>>>(x, nullptr, ln_att_g, ln_att_b, xnh, nullptr);

    // 2) QKV GEMM (fp16 in, fp16 out)
    h16_gemm_kernel<0, 1, false><<<dim3(1536 / 256, ROWS / 128), 256, GEMM_SMEM>>>(
        xnh, wt1, qkv_b, nullptr, qkvh, Emb, 3 * Emb);

    // 3) attention (fp16 mma, pipelined) -> fp32
    attn_h16_kernel<<<dim3(Nseq / 64, Bsz * Hn), 128, ATTN_SMEM>>>(qkvh, attn);

    // 4) residual + LN2 -> xn2 fp16, x1 fp32
    ln_kernel<<<ROWS, 256>>>(attn, x, ln_ffn_g, ln_ffn_b, xn2h, x1);

    // 5) FC1 + GELU (fp16 in, fp16 out)
    h16_gemm_kernel<1, 1, false><<<dim3(HID / 256, ROWS / 128), 256, GEMM_SMEM>>>(
        xn2h, wt2, fc1_b, nullptr, hidh, Emb, HID);

    // 6) FC2 + bias + residual (fp16 in, fp32 out)
    h16_gemm_kernel<0, 0, true><<<dim3(Emb / 256, ROWS / 128), 256, GEMM_SMEM>>>(
        hidh, wt3, fc2_b, x1, out, HID, Emb);
}